// round 3
// baseline (speedup 1.0000x reference)
#include <cuda_runtime.h>
#include <cstddef>

#define Bsz  1024
#define Tsz  128
#define Isz  128
#define Hsz  256
#define Ksz  8
#define E1sz 512
#define E2sz 256

typedef unsigned long long u64;

// ---------------------------------------------------------------------------
// f32x2 packed-FMA helpers (sm_100+): doubles fp32 FMA throughput
// ---------------------------------------------------------------------------
__device__ __forceinline__ u64 ffma2(u64 a, u64 b, u64 c){
    u64 d; asm("fma.rn.f32x2 %0, %1, %2, %3;" : "=l"(d) : "l"(a), "l"(b), "l"(c)); return d;
}
__device__ __forceinline__ void unpack2(u64 v, float& lo, float& hi){
    asm("mov.b64 {%0, %1}, %2;" : "=f"(lo), "=f"(hi) : "l"(v));
}
__device__ __forceinline__ float sigmoidf_(float x){
    return __fdividef(1.0f, 1.0f + __expf(-x));
}
__device__ __forceinline__ float tanhf_(float x){
    // accurate enough (~1e-7 rel) via MUFU ex2 + rcp; saturates correctly at +-inf
    return 1.0f - __fdividef(2.0f, __expf(2.0f * x) + 1.0f);
}

// ---------------------------------------------------------------------------
// Scratch (static __device__ arrays: no allocation inside kernel_launch)
// ---------------------------------------------------------------------------
__device__ float g_hl0[(size_t)Tsz * Bsz * Hsz];     // layer-0 outputs, all T (134 MB)
__device__ float g_h1buf[2][(size_t)Bsz * Hsz];      // layer-1 ping-pong
__device__ float g_q[Bsz * Ksz];
__device__ float g_e1[(size_t)Ksz * Bsz * E1sz];     // expert hidden 1
__device__ float g_e2[(size_t)Ksz * Bsz * E2sz];     // expert hidden 2

// ---------------------------------------------------------------------------
// Fused GRU step: one time step. CTA tile = 64 batch rows x 32 hidden cols,
// computes all 3 gates (r,z,n) for its tile, applies gate math in epilogue.
//   gi = x_t @ W_ih^T   (phase 1, K = KIN)
//   gh = h   @ W_hh^T   (phase 2, K = H; skipped when FIRST since h = 0)
//   r = sig(gi_r + bih_r + gh_r + bhh_r); z likewise
//   n = tanh(gi_n + bih_n + r*(gh_n + bhh_n)); h' = (1-z)n + z h
// Grid: (16, 8) = 128 CTAs, 256 threads.
// ---------------------------------------------------------------------------
template<int KIN, bool FIRST>
__global__ void __launch_bounds__(256) gru_step_kernel(
    const float* __restrict__ X, long xstride,
    const float* __restrict__ Wih, const float* __restrict__ Whh,
    const float* __restrict__ bih, const float* __restrict__ bhh,
    const float* __restrict__ Hprev, float* __restrict__ Hnew)
{
    __shared__ float2 As[32][64];      // A value duplicated: As[k][m] = {a,a}
    __shared__ float  Ws[3][32][32];   // Ws[gate][k][j], j = hidden col in tile
    __shared__ float  sB[6][32];       // bih_r,bih_z,bih_n,bhh_r,bhh_z,bhh_n

    const int tid = threadIdx.x;
    const int tx  = tid & 15;          // column pair: cols {2tx, 2tx+1}
    const int ty  = tid >> 4;          // rows {4ty .. 4ty+3}
    const int m0  = blockIdx.x * 64;
    const int n0  = blockIdx.y * 32;

    if (tid < 192){
        int g = tid >> 5, j = tid & 31;
        sB[g][j] = (g < 3) ? bih[g * Hsz + n0 + j] : bhh[(g - 3) * Hsz + n0 + j];
    }

    u64 accI[3][4], accH[3][4];
    #pragma unroll
    for (int g = 0; g < 3; g++)
        #pragma unroll
        for (int r = 0; r < 4; r++){ accI[g][r] = 0ull; accH[g][r] = 0ull; }

    // ---------------- phase 1: X @ Wih^T ----------------
    for (int kk = 0; kk < KIN; kk += 32){
        __syncthreads();
        {
            int row = tid >> 2;
            const float* ar = X + (size_t)(m0 + row) * (size_t)xstride + kk;
            #pragma unroll
            for (int hh = 0; hh < 2; hh++){
                int kb = ((tid & 3) << 2) + (hh << 4);
                float4 v = *reinterpret_cast<const float4*>(ar + kb);
                As[kb + 0][row] = make_float2(v.x, v.x);
                As[kb + 1][row] = make_float2(v.y, v.y);
                As[kb + 2][row] = make_float2(v.z, v.z);
                As[kb + 3][row] = make_float2(v.w, v.w);
            }
        }
        #pragma unroll
        for (int i = 0; i < 3; i++){
            int idx = tid + (i << 8);
            int g = idx >> 8, j = (idx >> 3) & 31, kq = idx & 7;
            float4 v = *reinterpret_cast<const float4*>(
                Wih + (size_t)(g * Hsz + n0 + j) * KIN + kk + (kq << 2));
            Ws[g][(kq << 2) + 0][j] = v.x;
            Ws[g][(kq << 2) + 1][j] = v.y;
            Ws[g][(kq << 2) + 2][j] = v.z;
            Ws[g][(kq << 2) + 3][j] = v.w;
        }
        __syncthreads();
        #pragma unroll 8
        for (int k = 0; k < 32; k++){
            u64 b0 = *reinterpret_cast<const u64*>(&Ws[0][k][tx << 1]);
            u64 b1 = *reinterpret_cast<const u64*>(&Ws[1][k][tx << 1]);
            u64 b2 = *reinterpret_cast<const u64*>(&Ws[2][k][tx << 1]);
            #pragma unroll
            for (int r = 0; r < 4; r++){
                u64 a = *reinterpret_cast<const u64*>(&As[k][(ty << 2) + r]);
                accI[0][r] = ffma2(a, b0, accI[0][r]);
                accI[1][r] = ffma2(a, b1, accI[1][r]);
                accI[2][r] = ffma2(a, b2, accI[2][r]);
            }
        }
    }

    // ---------------- phase 2: Hprev @ Whh^T ----------------
    if constexpr (!FIRST){
        for (int kk = 0; kk < Hsz; kk += 32){
            __syncthreads();
            {
                int row = tid >> 2;
                const float* ar = Hprev + (size_t)(m0 + row) * Hsz + kk;
                #pragma unroll
                for (int hh = 0; hh < 2; hh++){
                    int kb = ((tid & 3) << 2) + (hh << 4);
                    float4 v = *reinterpret_cast<const float4*>(ar + kb);
                    As[kb + 0][row] = make_float2(v.x, v.x);
                    As[kb + 1][row] = make_float2(v.y, v.y);
                    As[kb + 2][row] = make_float2(v.z, v.z);
                    As[kb + 3][row] = make_float2(v.w, v.w);
                }
            }
            #pragma unroll
            for (int i = 0; i < 3; i++){
                int idx = tid + (i << 8);
                int g = idx >> 8, j = (idx >> 3) & 31, kq = idx & 7;
                float4 v = *reinterpret_cast<const float4*>(
                    Whh + (size_t)(g * Hsz + n0 + j) * Hsz + kk + (kq << 2));
                Ws[g][(kq << 2) + 0][j] = v.x;
                Ws[g][(kq << 2) + 1][j] = v.y;
                Ws[g][(kq << 2) + 2][j] = v.z;
                Ws[g][(kq << 2) + 3][j] = v.w;
            }
            __syncthreads();
            #pragma unroll 8
            for (int k = 0; k < 32; k++){
                u64 b0 = *reinterpret_cast<const u64*>(&Ws[0][k][tx << 1]);
                u64 b1 = *reinterpret_cast<const u64*>(&Ws[1][k][tx << 1]);
                u64 b2 = *reinterpret_cast<const u64*>(&Ws[2][k][tx << 1]);
                #pragma unroll
                for (int r = 0; r < 4; r++){
                    u64 a = *reinterpret_cast<const u64*>(&As[k][(ty << 2) + r]);
                    accH[0][r] = ffma2(a, b0, accH[0][r]);
                    accH[1][r] = ffma2(a, b1, accH[1][r]);
                    accH[2][r] = ffma2(a, b2, accH[2][r]);
                }
            }
        }
    }

    // ---------------- epilogue: gate math ----------------
    #pragma unroll
    for (int r = 0; r < 4; r++){
        int row = m0 + (ty << 2) + r;
        float giv[3][2], ghv[3][2];
        #pragma unroll
        for (int g = 0; g < 3; g++){
            unpack2(accI[g][r], giv[g][0], giv[g][1]);
            if constexpr (FIRST){ ghv[g][0] = 0.0f; ghv[g][1] = 0.0f; }
            else                { unpack2(accH[g][r], ghv[g][0], ghv[g][1]); }
        }
        float2 hp = make_float2(0.0f, 0.0f);
        if constexpr (!FIRST)
            hp = *reinterpret_cast<const float2*>(&Hprev[(size_t)row * Hsz + n0 + (tx << 1)]);
        float outv[2];
        #pragma unroll
        for (int c = 0; c < 2; c++){
            int j = (tx << 1) + c;
            float rg = sigmoidf_(giv[0][c] + sB[0][j] + ghv[0][c] + sB[3][j]);
            float zg = sigmoidf_(giv[1][c] + sB[1][j] + ghv[1][c] + sB[4][j]);
            float ng = tanhf_(giv[2][c] + sB[2][j] + rg * (ghv[2][c] + sB[5][j]));
            float hpv = c ? hp.y : hp.x;
            outv[c] = (1.0f - zg) * ng + zg * hpv;
        }
        *reinterpret_cast<float2*>(&Hnew[(size_t)row * Hsz + n0 + (tx << 1)]) =
            make_float2(outv[0], outv[1]);
    }
}

// ---------------------------------------------------------------------------
// Generic per-expert GEMM: C[e] = relu(A[e] @ W[e]^T + bias[e])
// A row-major [M,Kdim], W row-major [Ndim,Kdim]. Tile 64x64, 256 threads.
// ---------------------------------------------------------------------------
__global__ void __launch_bounds__(256) gemm_relu_kernel(
    const float* __restrict__ Abase, size_t aStride,
    const float* __restrict__ Wbase, size_t wStride,
    const float* __restrict__ biasBase, size_t bStride,
    float* __restrict__ Cbase, size_t cStride,
    int Kdim, int Ndim)
{
    const int e = blockIdx.z;
    const float* A    = Abase    + (size_t)e * aStride;
    const float* W    = Wbase    + (size_t)e * wStride;
    const float* bias = biasBase + (size_t)e * bStride;
    float*       C    = Cbase    + (size_t)e * cStride;

    const int m0 = blockIdx.x * 64, n0 = blockIdx.y * 64;
    const int tid = threadIdx.x, tx = tid & 15, ty = tid >> 4;

    __shared__ float2 As[32][64];
    __shared__ float  Ws[32][64];

    u64 acc[4][2];
    #pragma unroll
    for (int r = 0; r < 4; r++){ acc[r][0] = 0ull; acc[r][1] = 0ull; }

    for (int kk = 0; kk < Kdim; kk += 32){
        __syncthreads();
        {
            int row = tid >> 2;
            const float* ar = A + (size_t)(m0 + row) * Kdim + kk;
            const float* wr = W + (size_t)(n0 + row) * Kdim + kk;
            #pragma unroll
            for (int hh = 0; hh < 2; hh++){
                int kb = ((tid & 3) << 2) + (hh << 4);
                float4 va = *reinterpret_cast<const float4*>(ar + kb);
                As[kb + 0][row] = make_float2(va.x, va.x);
                As[kb + 1][row] = make_float2(va.y, va.y);
                As[kb + 2][row] = make_float2(va.z, va.z);
                As[kb + 3][row] = make_float2(va.w, va.w);
                float4 vw = *reinterpret_cast<const float4*>(wr + kb);
                Ws[kb + 0][row] = vw.x;
                Ws[kb + 1][row] = vw.y;
                Ws[kb + 2][row] = vw.z;
                Ws[kb + 3][row] = vw.w;
            }
        }
        __syncthreads();
        #pragma unroll 8
        for (int k = 0; k < 32; k++){
            u64 b0 = *reinterpret_cast<const u64*>(&Ws[k][tx << 1]);
            u64 b1 = *reinterpret_cast<const u64*>(&Ws[k][(tx << 1) + 32]);
            #pragma unroll
            for (int r = 0; r < 4; r++){
                u64 a = *reinterpret_cast<const u64*>(&As[k][(ty << 2) + r]);
                acc[r][0] = ffma2(a, b0, acc[r][0]);
                acc[r][1] = ffma2(a, b1, acc[r][1]);
            }
        }
    }

    #pragma unroll
    for (int r = 0; r < 4; r++){
        int row = m0 + (ty << 2) + r;
        #pragma unroll
        for (int p = 0; p < 2; p++){
            int j = (tx << 1) + (p << 5);
            float c0, c1;
            unpack2(acc[r][p], c0, c1);
            c0 = fmaxf(c0 + bias[n0 + j],     0.0f);
            c1 = fmaxf(c1 + bias[n0 + j + 1], 0.0f);
            *reinterpret_cast<float2*>(&C[(size_t)row * Ndim + n0 + j]) = make_float2(c0, c1);
        }
    }
}

// ---------------------------------------------------------------------------
// Soft cluster assignment q (Student-t, alpha=1). One warp per batch row.
// ---------------------------------------------------------------------------
__global__ void __launch_bounds__(256) qkernel(
    const float* __restrict__ z, const float* __restrict__ cent, float* __restrict__ q)
{
    int warp = threadIdx.x >> 5, lane = threadIdx.x & 31;
    int b = blockIdx.x * 8 + warp;
    float zr[8];
    #pragma unroll
    for (int i = 0; i < 8; i++) zr[i] = z[(size_t)b * Hsz + lane + 32 * i];
    float s = 0.0f;
    for (int k = 0; k < Ksz; k++){
        float d = 0.0f;
        #pragma unroll
        for (int i = 0; i < 8; i++){
            float t = zr[i] - cent[k * Hsz + lane + 32 * i];
            d = fmaf(t, t, d);
        }
        #pragma unroll
        for (int off = 16; off; off >>= 1) d += __shfl_xor_sync(0xffffffffu, d, off);
        if (lane == k) s = 1.0f / (1.0f + d);
    }
    float tot = s;
    #pragma unroll
    for (int off = 16; off; off >>= 1) tot += __shfl_xor_sync(0xffffffffu, tot, off);
    if (lane < Ksz) q[(size_t)b * Ksz + lane] = s / tot;
}

// ---------------------------------------------------------------------------
// logits + q-weighted combine. One warp per batch row.
// preds[b,c] = sum_k q[b,k] * (h2[b,k,:] . eW3[k,c,:] + eb3[k,c])
// ---------------------------------------------------------------------------
__global__ void __launch_bounds__(256) combine_kernel(
    const float* __restrict__ h2, const float* __restrict__ q,
    const float* __restrict__ eW3, const float* __restrict__ eb3,
    float* __restrict__ out)
{
    int warp = threadIdx.x >> 5, lane = threadIdx.x & 31;
    int b = blockIdx.x * 8 + warp;
    float acc[Ksz][2];
    #pragma unroll
    for (int k = 0; k < Ksz; k++){ acc[k][0] = 0.0f; acc[k][1] = 0.0f; }
    for (int f = lane; f < E2sz; f += 32){
        #pragma unroll
        for (int k = 0; k < Ksz; k++){
            float hv = h2[((size_t)k * Bsz + b) * E2sz + f];
            acc[k][0] = fmaf(hv, eW3[(size_t)(k * 2 + 0) * E2sz + f], acc[k][0]);
            acc[k][1] = fmaf(hv, eW3[(size_t)(k * 2 + 1) * E2sz + f], acc[k][1]);
        }
    }
    #pragma unroll
    for (int k = 0; k < Ksz; k++)
        #pragma unroll
        for (int c = 0; c < 2; c++)
            #pragma unroll
            for (int off = 16; off; off >>= 1)
                acc[k][c] += __shfl_xor_sync(0xffffffffu, acc[k][c], off);
    if (lane == 0){
        float p0 = 0.0f, p1 = 0.0f;
        #pragma unroll
        for (int k = 0; k < Ksz; k++){
            float qq = q[(size_t)b * Ksz + k];
            p0 = fmaf(qq, acc[k][0] + eb3[k * 2 + 0], p0);
            p1 = fmaf(qq, acc[k][1] + eb3[k * 2 + 1], p1);
        }
        out[b * 2 + 0] = p0;
        out[b * 2 + 1] = p1;
    }
}

// ---------------------------------------------------------------------------
// kernel_launch: graph of ~260 kernel nodes, all on the capture stream
// ---------------------------------------------------------------------------
extern "C" void kernel_launch(void* const* d_in, const int* in_sizes, int n_in,
                              void* d_out, int out_size)
{
    const float* x    = (const float*)d_in[0];
    const float* Wih0 = (const float*)d_in[1];
    const float* Whh0 = (const float*)d_in[2];
    const float* bih0 = (const float*)d_in[3];
    const float* bhh0 = (const float*)d_in[4];
    const float* Wih1 = (const float*)d_in[5];
    const float* Whh1 = (const float*)d_in[6];
    const float* bih1 = (const float*)d_in[7];
    const float* bhh1 = (const float*)d_in[8];
    const float* cent = (const float*)d_in[9];
    const float* eW1  = (const float*)d_in[10];
    const float* eb1  = (const float*)d_in[11];
    const float* eW2  = (const float*)d_in[12];
    const float* eb2  = (const float*)d_in[13];
    const float* eW3  = (const float*)d_in[14];
    const float* eb3  = (const float*)d_in[15];
    float* out = (float*)d_out;

    float *hl0, *h1, *qb, *e1, *e2;
    cudaGetSymbolAddress((void**)&hl0, g_hl0);
    cudaGetSymbolAddress((void**)&h1,  g_h1buf);
    cudaGetSymbolAddress((void**)&qb,  g_q);
    cudaGetSymbolAddress((void**)&e1,  g_e1);
    cudaGetSymbolAddress((void**)&e2,  g_e2);

    dim3 sg(16, 8);

    // ---- layer 0: h_l0[t] stored for all t (layer-1 inputs) ----
    gru_step_kernel<Isz, true><<<sg, 256>>>(
        x, (long)(Tsz * Isz), Wih0, Whh0, bih0, bhh0, hl0, hl0);
    for (int t = 1; t < Tsz; t++){
        gru_step_kernel<Isz, false><<<sg, 256>>>(
            x + (size_t)t * Isz, (long)(Tsz * Isz), Wih0, Whh0, bih0, bhh0,
            hl0 + (size_t)(t - 1) * Bsz * Hsz, hl0 + (size_t)t * Bsz * Hsz);
    }

    // ---- layer 1: ping-pong buffers; t writes buf[(t+1)&1]; final z = buf[0] ----
    gru_step_kernel<Hsz, true><<<sg, 256>>>(
        hl0, (long)Hsz, Wih1, Whh1, bih1, bhh1, h1, h1 + (size_t)Bsz * Hsz);
    for (int t = 1; t < Tsz; t++){
        gru_step_kernel<Hsz, false><<<sg, 256>>>(
            hl0 + (size_t)t * Bsz * Hsz, (long)Hsz, Wih1, Whh1, bih1, bhh1,
            h1 + (size_t)(t & 1) * Bsz * Hsz, h1 + (size_t)((t + 1) & 1) * Bsz * Hsz);
    }
    const float* z = h1;   // buf[0] after 128 steps

    // ---- soft clustering ----
    qkernel<<<128, 256>>>(z, cent, qb);

    // ---- experts: h1 = relu(z @ eW1^T + eb1); h2 = relu(h1 @ eW2^T + eb2) ----
    gemm_relu_kernel<<<dim3(16, 8, 8), 256>>>(
        z, (size_t)0,
        eW1, (size_t)E1sz * Hsz,
        eb1, (size_t)E1sz,
        e1,  (size_t)Bsz * E1sz,
        Hsz, E1sz);
    gemm_relu_kernel<<<dim3(16, 4, 8), 256>>>(
        e1, (size_t)Bsz * E1sz,
        eW2, (size_t)E2sz * E1sz,
        eb2, (size_t)E2sz,
        e2,  (size_t)Bsz * E2sz,
        E1sz, E2sz);

    // ---- logits + q-weighted combine ----
    combine_kernel<<<128, 256>>>(e2, qb, eW3, eb3, out);

    (void)in_sizes; (void)n_in; (void)out_size;
}